// round 6
// baseline (speedup 1.0000x reference)
#include <cuda_runtime.h>
#include <cuda_fp16.h>
#include <cstdint>

#define N_ENTITIES 100000
#define N_USERS    50000
#define N_ITEMS    30000
#define D          64
#define N_REL      16
#define N_FACTORS  4
#define N_CLUSTERS 4
#define N_EDGES    1500000
#define NNZ_IM     1000000
#define NNZ_ICM    1000000
#define N_HOPS     2
#define TMP        0.2f

#define N_SEGS     (N_ENTITIES + N_USERS + N_USERS)   // 200000
#define IM_SEG0    N_ENTITIES
#define ICM_SEG0   (N_ENTITIES + N_USERS)
#define IM_BASE    N_EDGES
#define ICM_BASE   (N_EDGES + NNZ_IM)
#define TOT_NNZ    (N_EDGES + NNZ_IM + NNZ_ICM)       // 3.5M

#define SCAN_TILE  1024
#define N_TILES    ((N_SEGS + SCAN_TILE - 1) / SCAN_TILE)   // 196

#define CONV_N     (N_ENTITIES * D / 2)                // 3.2M half2 elems

// ---------------- scratch ----------------
__device__ float  g_att [N_ENTITIES * N_REL];
__device__ float  g_ucls[N_USERS * N_CLUSTERS];
__device__ __half g_ehA [N_ENTITIES * D];
__device__ __half g_ehB [N_ENTITIES * D];
__device__ float  g_u   [N_USERS * D];
__device__ float  g_relsum[D];

__device__ int   g_counts  [N_SEGS];
__device__ int   g_offsets [N_SEGS];
__device__ int   g_cursor  [N_SEGS];
__device__ int   g_tilesum [N_TILES];
__device__ int   g_tilebase[N_TILES];
__device__ int2  g_edge [N_EDGES];   // {tail | etype<<20, imp bits}
__device__ int2  g_im   [NNZ_IM];    // {col, val bits}
__device__ int2  g_icm  [NNZ_ICM];   // {col | cls<<16, val bits}

// ---------------- prep: convert fp32->fp16 + zero counts + relsum ----------------
__global__ void prep_kernel(const float2* __restrict__ e2, __half2* __restrict__ eh,
                            const float* __restrict__ rel) {
    int i = blockIdx.x * blockDim.x + threadIdx.x;
    if (i < CONV_N) eh[i] = __float22half2_rn(e2[i]);
    if (i < N_SEGS) g_counts[i] = 0;
    if (i < D) {
        float s = 0.f;
#pragma unroll
        for (int r = 0; r < N_REL; r++) s += rel[r * D + i];
        g_relsum[i] = s;
    }
}

// ---------------- build ----------------
__global__ void count_kernel(const int* __restrict__ head,
                             const int* __restrict__ im_rows,
                             const int* __restrict__ icm_rows) {
    int i = blockIdx.x * blockDim.x + threadIdx.x;
    if (i < N_EDGES) {
        atomicAdd(&g_counts[head[i]], 1);
    } else if (i < N_EDGES + NNZ_IM) {
        atomicAdd(&g_counts[IM_SEG0 + im_rows[i - N_EDGES]], 1);
    } else if (i < TOT_NNZ) {
        atomicAdd(&g_counts[ICM_SEG0 + icm_rows[i - N_EDGES - NNZ_IM]], 1);
    }
}

__global__ void scanA_kernel() {
    __shared__ int s[SCAN_TILE];
    int idx = blockIdx.x * SCAN_TILE + threadIdx.x;
    s[threadIdx.x] = (idx < N_SEGS) ? g_counts[idx] : 0;
    __syncthreads();
    for (int off = SCAN_TILE / 2; off > 0; off >>= 1) {
        if (threadIdx.x < off) s[threadIdx.x] += s[threadIdx.x + off];
        __syncthreads();
    }
    if (threadIdx.x == 0) g_tilesum[blockIdx.x] = s[0];
}

__global__ void scanB_kernel() {
    __shared__ int s[256];
    int t = threadIdx.x;
    int v = (t < N_TILES) ? g_tilesum[t] : 0;
    s[t] = v;
    __syncthreads();
    for (int off = 1; off < 256; off <<= 1) {
        int w = (t >= off) ? s[t - off] : 0;
        __syncthreads();
        s[t] += w;
        __syncthreads();
    }
    if (t < N_TILES) g_tilebase[t] = s[t] - v;
}

__global__ void scanC_kernel() {
    __shared__ int s[SCAN_TILE];
    int t = threadIdx.x;
    int idx = blockIdx.x * SCAN_TILE + t;
    int v = (idx < N_SEGS) ? g_counts[idx] : 0;
    s[t] = v;
    __syncthreads();
    for (int off = 1; off < SCAN_TILE; off <<= 1) {
        int w = (t >= off) ? s[t - off] : 0;
        __syncthreads();
        s[t] += w;
        __syncthreads();
    }
    if (idx < N_SEGS) {
        int excl = g_tilebase[blockIdx.x] + s[t] - v;
        g_offsets[idx] = excl;
        g_cursor[idx]  = excl;
    }
}

__global__ void fill_kernel(const int* __restrict__ head, const int* __restrict__ tail,
                            const int* __restrict__ etype, const float* __restrict__ eimp,
                            const int* __restrict__ im_rows, const int* __restrict__ im_cols,
                            const float* __restrict__ im_vals,
                            const int* __restrict__ icm_rows, const int* __restrict__ icm_cols,
                            const int* __restrict__ icm_cls, const float* __restrict__ icm_vals) {
    int i = blockIdx.x * blockDim.x + threadIdx.x;
    if (i < N_EDGES) {
        int h = head[i];
        int pos = atomicAdd(&g_cursor[h], 1);
        g_edge[pos] = make_int2(tail[i] | (etype[i] << 20), __float_as_int(eimp[i]));
    } else if (i < N_EDGES + NNZ_IM) {
        int j = i - N_EDGES;
        int r = im_rows[j];
        int pos = atomicAdd(&g_cursor[IM_SEG0 + r], 1) - IM_BASE;
        g_im[pos] = make_int2(im_cols[j], __float_as_int(im_vals[j]));
    } else if (i < TOT_NNZ) {
        int j = i - N_EDGES - NNZ_IM;
        int r = icm_rows[j];
        int pos = atomicAdd(&g_cursor[ICM_SEG0 + r], 1) - ICM_BASE;
        g_icm[pos] = make_int2(icm_cols[j] | (icm_cls[j] << 16), __float_as_int(icm_vals[j]));
    }
}

// ---------------- hop-0 att/ucls (from fp32 inputs) ----------------
__global__ void attucls_kernel(const float* __restrict__ e, const float* __restrict__ u,
                               const float* __restrict__ rel, const float* __restrict__ w) {
    __shared__ float s_rel[N_REL * D];
    __shared__ float s_w[N_CLUSTERS * D];
    for (int i = threadIdx.x; i < N_REL * D; i += blockDim.x) s_rel[i] = rel[i];
    for (int i = threadIdx.x; i < N_CLUSTERS * D; i += blockDim.x) s_w[i] = w[i];
    __syncthreads();
    int i = blockIdx.x * blockDim.x + threadIdx.x;
    if (i < N_ENTITIES) {
        const float4* row = (const float4*)(e + (size_t)i * D);
        float acc[N_REL];
#pragma unroll
        for (int r = 0; r < N_REL; r++) acc[r] = 0.f;
#pragma unroll
        for (int k = 0; k < D / 4; k++) {
            float4 ev = row[k];
#pragma unroll
            for (int r = 0; r < N_REL; r++) {
                float4 rv = ((const float4*)(s_rel + r * D))[k];
                acc[r] += ev.x * rv.x + ev.y * rv.y + ev.z * rv.z + ev.w * rv.w;
            }
        }
        float mx = acc[0];
#pragma unroll
        for (int r = 1; r < N_REL; r++) mx = fmaxf(mx, acc[r]);
        float sum = 0.f;
#pragma unroll
        for (int r = 0; r < N_REL; r++) { acc[r] = expf(acc[r] - mx); sum += acc[r]; }
        float inv = 1.f / sum;
#pragma unroll
        for (int r = 0; r < N_REL; r++) g_att[(size_t)i * N_REL + r] = acc[r] * inv;
    } else if (i < N_ENTITIES + N_USERS) {
        int uidx = i - N_ENTITIES;
        const float4* row = (const float4*)(u + (size_t)uidx * D);
        float acc[N_CLUSTERS] = {0.f, 0.f, 0.f, 0.f};
#pragma unroll
        for (int k = 0; k < D / 4; k++) {
            float4 uv = row[k];
#pragma unroll
            for (int c = 0; c < N_CLUSTERS; c++) {
                float4 wv = ((const float4*)(s_w + c * D))[k];
                acc[c] += uv.x * wv.x + uv.y * wv.y + uv.z * wv.z + uv.w * wv.w;
            }
        }
        float mx = fmaxf(fmaxf(acc[0], acc[1]), fmaxf(acc[2], acc[3]));
        float sum = 0.f;
#pragma unroll
        for (int c = 0; c < N_CLUSTERS; c++) { acc[c] = expf(acc[c] - mx); sum += acc[c]; }
        float inv = 1.f / sum;
#pragma unroll
        for (int c = 0; c < N_CLUSTERS; c++) g_ucls[(size_t)uidx * N_CLUSTERS + c] = acc[c] * inv;
    }
}

// ---------------- fused gather (warp per row; fp16 gathers; epilogue att/ucls for next hop) ----
template <bool HOP0>
__global__ void gather_kernel(const __half2* __restrict__ eh,
                              const float* __restrict__ rel,
                              const float* __restrict__ wcls,
                              __half2* __restrict__ eh_out,
                              const float2* __restrict__ base_ent, float2* __restrict__ res_ent,
                              float* __restrict__ u_out,
                              const float2* __restrict__ base_usr, float2* __restrict__ res_usr) {
    __shared__ float2 s_rel[N_REL * 32];
    __shared__ float2 s_w2[N_CLUSTERS * 32];
    __shared__ float2 s_rs[32];
    for (int i = threadIdx.x; i < N_REL * 32; i += blockDim.x)
        s_rel[i] = ((const float2*)rel)[i];
    for (int i = threadIdx.x; i < N_CLUSTERS * 32; i += blockDim.x)
        s_w2[i] = ((const float2*)wcls)[i];
    if (threadIdx.x < 32) s_rs[threadIdx.x] = ((const float2*)g_relsum)[threadIdx.x];
    __syncthreads();

    int warp = (blockIdx.x * blockDim.x + threadIdx.x) >> 5;
    int lane = threadIdx.x & 31;
    float2 acc = make_float2(0.f, 0.f);

    if (warp < N_ENTITIES) {
        int start = g_offsets[warp];
        int cnt   = g_counts[warp];
        const int2* ep = g_edge + start;
        const float* attrow = g_att + (size_t)warp * N_REL;
        int j = 0;
        for (; j + 4 <= cnt; j += 4) {
            int2 a0 = ep[j], a1 = ep[j + 1], a2 = ep[j + 2], a3 = ep[j + 3];
            int t0 = a0.x & 0xFFFFF, r0 = a0.x >> 20;
            int t1 = a1.x & 0xFFFFF, r1 = a1.x >> 20;
            int t2 = a2.x & 0xFFFFF, r2 = a2.x >> 20;
            int t3 = a3.x & 0xFFFFF, r3 = a3.x >> 20;
            float w0 = __int_as_float(a0.y) * attrow[r0];
            float w1 = __int_as_float(a1.y) * attrow[r1];
            float w2 = __int_as_float(a2.y) * attrow[r2];
            float w3 = __int_as_float(a3.y) * attrow[r3];
            float2 v0 = __half22float2(eh[(size_t)t0 * 32 + lane]);
            float2 v1 = __half22float2(eh[(size_t)t1 * 32 + lane]);
            float2 v2 = __half22float2(eh[(size_t)t2 * 32 + lane]);
            float2 v3 = __half22float2(eh[(size_t)t3 * 32 + lane]);
            float2 q0 = s_rel[r0 * 32 + lane];
            float2 q1 = s_rel[r1 * 32 + lane];
            float2 q2 = s_rel[r2 * 32 + lane];
            float2 q3 = s_rel[r3 * 32 + lane];
            acc.x += w0 * v0.x * q0.x + w1 * v1.x * q1.x + w2 * v2.x * q2.x + w3 * v3.x * q3.x;
            acc.y += w0 * v0.y * q0.y + w1 * v1.y * q1.y + w2 * v2.y * q2.y + w3 * v3.y * q3.y;
        }
        for (; j < cnt; j++) {
            int2 a = ep[j];
            int t = a.x & 0xFFFFF, r = a.x >> 20;
            float wv = __int_as_float(a.y) * attrow[r];
            float2 v = __half22float2(eh[(size_t)t * 32 + lane]);
            float2 q = s_rel[r * 32 + lane];
            acc.x += wv * v.x * q.x;
            acc.y += wv * v.y * q.y;
        }
        float ss = acc.x * acc.x + acc.y * acc.y;
#pragma unroll
        for (int o = 16; o; o >>= 1) ss += __shfl_xor_sync(0xffffffffu, ss, o);
        float inv = 1.f / fmaxf(sqrtf(ss), 1e-12f);
        float2 o2 = make_float2(acc.x * inv, acc.y * inv);
        eh_out[(size_t)warp * 32 + lane] = __float22half2_rn(o2);
        float2 cur = HOP0 ? base_ent[(size_t)warp * 32 + lane]
                          : res_ent[(size_t)warp * 32 + lane];
        cur.x += o2.x; cur.y += o2.y;
        res_ent[(size_t)warp * 32 + lane] = cur;

        if (HOP0) {
            // next-hop att for this row, from fp32 o2
            float p[N_REL];
#pragma unroll
            for (int r = 0; r < N_REL; r++) {
                float2 q = s_rel[r * 32 + lane];
                p[r] = o2.x * q.x + o2.y * q.y;
            }
#pragma unroll
            for (int r = 0; r < N_REL; r++) {
#pragma unroll
                for (int o = 16; o; o >>= 1)
                    p[r] += __shfl_xor_sync(0xffffffffu, p[r], o);
            }
            float mx = p[0];
#pragma unroll
            for (int r = 1; r < N_REL; r++) mx = fmaxf(mx, p[r]);
            float sum = 0.f;
#pragma unroll
            for (int r = 0; r < N_REL; r++) { p[r] = expf(p[r] - mx); sum += p[r]; }
            float sinv = 1.f / sum;
            if (lane == 0) {
                float4* ap = (float4*)(g_att + (size_t)warp * N_REL);
                ap[0] = make_float4(p[0] * sinv,  p[1] * sinv,  p[2] * sinv,  p[3] * sinv);
                ap[1] = make_float4(p[4] * sinv,  p[5] * sinv,  p[6] * sinv,  p[7] * sinv);
                ap[2] = make_float4(p[8] * sinv,  p[9] * sinv,  p[10] * sinv, p[11] * sinv);
                ap[3] = make_float4(p[12] * sinv, p[13] * sinv, p[14] * sinv, p[15] * sinv);
            }
        }
    } else if (warp < N_ENTITIES + N_USERS) {
        int uidx = warp - N_ENTITIES;
        float2 rs = s_rs[lane];
        const float* ucrow = g_ucls + (size_t)uidx * N_CLUSTERS;
        // im segment
        {
            int start = g_offsets[IM_SEG0 + uidx] - IM_BASE;
            int cnt   = g_counts[IM_SEG0 + uidx];
            const int2* ep = g_im + start;
            int j = 0;
            for (; j + 4 <= cnt; j += 4) {
                int2 a0 = ep[j], a1 = ep[j + 1], a2 = ep[j + 2], a3 = ep[j + 3];
                float2 v0 = __half22float2(eh[(size_t)a0.x * 32 + lane]);
                float2 v1 = __half22float2(eh[(size_t)a1.x * 32 + lane]);
                float2 v2 = __half22float2(eh[(size_t)a2.x * 32 + lane]);
                float2 v3 = __half22float2(eh[(size_t)a3.x * 32 + lane]);
                float w0 = __int_as_float(a0.y), w1 = __int_as_float(a1.y);
                float w2 = __int_as_float(a2.y), w3 = __int_as_float(a3.y);
                acc.x += w0 * v0.x + w1 * v1.x + w2 * v2.x + w3 * v3.x;
                acc.y += w0 * v0.y + w1 * v1.y + w2 * v2.y + w3 * v3.y;
            }
            for (; j < cnt; j++) {
                int2 a = ep[j];
                float2 v = __half22float2(eh[(size_t)a.x * 32 + lane]);
                float w = __int_as_float(a.y);
                acc.x += w * v.x;
                acc.y += w * v.y;
            }
        }
        // icm segment
        float2 acc2 = make_float2(0.f, 0.f);
        {
            int start = g_offsets[ICM_SEG0 + uidx] - ICM_BASE;
            int cnt   = g_counts[ICM_SEG0 + uidx];
            const int2* ep = g_icm + start;
            int j = 0;
            for (; j + 4 <= cnt; j += 4) {
                int2 a0 = ep[j], a1 = ep[j + 1], a2 = ep[j + 2], a3 = ep[j + 3];
                int c0 = a0.x & 0xFFFF, k0 = a0.x >> 16;
                int c1 = a1.x & 0xFFFF, k1 = a1.x >> 16;
                int c2 = a2.x & 0xFFFF, k2 = a2.x >> 16;
                int c3 = a3.x & 0xFFFF, k3 = a3.x >> 16;
                float w0 = __int_as_float(a0.y) * ucrow[k0];
                float w1 = __int_as_float(a1.y) * ucrow[k1];
                float w2 = __int_as_float(a2.y) * ucrow[k2];
                float w3 = __int_as_float(a3.y) * ucrow[k3];
                float2 v0 = __half22float2(eh[(size_t)c0 * 32 + lane]);
                float2 v1 = __half22float2(eh[(size_t)c1 * 32 + lane]);
                float2 v2 = __half22float2(eh[(size_t)c2 * 32 + lane]);
                float2 v3 = __half22float2(eh[(size_t)c3 * 32 + lane]);
                acc2.x += w0 * v0.x + w1 * v1.x + w2 * v2.x + w3 * v3.x;
                acc2.y += w0 * v0.y + w1 * v1.y + w2 * v2.y + w3 * v3.y;
            }
            for (; j < cnt; j++) {
                int2 a = ep[j];
                int c = a.x & 0xFFFF, k = a.x >> 16;
                float w = __int_as_float(a.y) * ucrow[k];
                float2 v = __half22float2(eh[(size_t)c * 32 + lane]);
                acc2.x += w * v.x;
                acc2.y += w * v.y;
            }
        }
        acc.x += acc2.x * rs.x;
        acc.y += acc2.y * rs.y;

        float ss = acc.x * acc.x + acc.y * acc.y;
#pragma unroll
        for (int o = 16; o; o >>= 1) ss += __shfl_xor_sync(0xffffffffu, ss, o);
        float inv = 1.f / fmaxf(sqrtf(ss), 1e-12f);
        float2 o2 = make_float2(acc.x * inv, acc.y * inv);
        ((float2*)(u_out + (size_t)uidx * D))[lane] = o2;
        float2 cur = HOP0 ? base_usr[(size_t)uidx * 32 + lane]
                          : res_usr[(size_t)uidx * 32 + lane];
        cur.x += o2.x; cur.y += o2.y;
        res_usr[(size_t)uidx * 32 + lane] = cur;

        if (HOP0) {
            // next-hop ucls for this user
            float p[N_CLUSTERS];
#pragma unroll
            for (int c = 0; c < N_CLUSTERS; c++) {
                float2 q = s_w2[c * 32 + lane];
                p[c] = o2.x * q.x + o2.y * q.y;
            }
#pragma unroll
            for (int c = 0; c < N_CLUSTERS; c++) {
#pragma unroll
                for (int o = 16; o; o >>= 1)
                    p[c] += __shfl_xor_sync(0xffffffffu, p[c], o);
            }
            float mx = fmaxf(fmaxf(p[0], p[1]), fmaxf(p[2], p[3]));
            float sum = 0.f;
#pragma unroll
            for (int c = 0; c < N_CLUSTERS; c++) { p[c] = expf(p[c] - mx); sum += p[c]; }
            float sinv = 1.f / sum;
            if (lane == 0) {
                *(float4*)(g_ucls + (size_t)uidx * N_CLUSTERS) =
                    make_float4(p[0] * sinv, p[1] * sinv, p[2] * sinv, p[3] * sinv);
            }
        }
    }
}

// ---------------- cor loss ----------------
__global__ void cor_kernel(const float* __restrict__ dw, float* __restrict__ out) {
    float nt[N_FACTORS][N_REL];
#pragma unroll
    for (int c = 0; c < N_FACTORS; c++) {
        float ss = 0.f;
#pragma unroll
        for (int k = 0; k < N_REL; k++) { float x = dw[c * N_REL + k]; ss += x * x; }
        float inv = 1.f / fmaxf(sqrtf(ss), 1e-12f);
#pragma unroll
        for (int k = 0; k < N_REL; k++) nt[c][k] = dw[c * N_REL + k] * inv;
    }
    float loss = 0.f;
#pragma unroll
    for (int i = 0; i < N_FACTORS; i++) {
        float ssum = 0.f, diag = 0.f;
#pragma unroll
        for (int j = 0; j < N_FACTORS; j++) {
            float dot = 0.f;
#pragma unroll
            for (int k = 0; k < N_REL; k++) dot += nt[i][k] * nt[j][k];
            float s = expf(dot / TMP);
            ssum += s;
            if (i == j) diag = s;
        }
        loss -= logf(diag / ssum);
    }
    out[0] = loss;
}

// ---------------- launch ----------------
extern "C" void kernel_launch(void* const* d_in, const int* in_sizes, int n_in,
                              void* d_out, int out_size) {
    const float* user_emb     = (const float*)d_in[0];
    const float* entity_emb   = (const float*)d_in[1];
    const float* relation_emb = (const float*)d_in[3];
    const float* disen        = (const float*)d_in[4];
    const float* usr_cls_w    = (const float*)d_in[5];
    const float* edge_imp     = (const float*)d_in[6];
    const float* im_vals      = (const float*)d_in[7];
    const float* icm_vals     = (const float*)d_in[8];
    const int*   edge_index   = (const int*)d_in[9];
    const int*   edge_type    = (const int*)d_in[10];
    const int*   im_rows      = (const int*)d_in[11];
    const int*   im_cols      = (const int*)d_in[12];
    const int*   icm_cls      = (const int*)d_in[13];
    const int*   icm_rows     = (const int*)d_in[14];
    const int*   icm_cols     = (const int*)d_in[15];

    float* out     = (float*)d_out;
    float* out_ent = out;
    float* out_usr = out + (size_t)N_ENTITIES * D;
    float* out_cor = out + (size_t)N_ENTITIES * D + (size_t)N_USERS * D;

    __half *p_ehA, *p_ehB;
    float *p_u;
    cudaGetSymbolAddress((void**)&p_ehA, g_ehA);
    cudaGetSymbolAddress((void**)&p_ehB, g_ehB);
    cudaGetSymbolAddress((void**)&p_u, g_u);

    const int TPB = 256;

    // prep: fp16 convert + zero counts + relsum (one kernel)
    prep_kernel<<<(CONV_N + TPB - 1) / TPB, TPB>>>(
        (const float2*)entity_emb, (__half2*)p_ehA, relation_emb);

    // CSR build
    count_kernel<<<(TOT_NNZ + TPB - 1) / TPB, TPB>>>(edge_index, im_rows, icm_rows);
    scanA_kernel<<<N_TILES, SCAN_TILE>>>();
    scanB_kernel<<<1, 256>>>();
    scanC_kernel<<<N_TILES, SCAN_TILE>>>();
    fill_kernel<<<(TOT_NNZ + TPB - 1) / TPB, TPB>>>(
        edge_index, edge_index + N_EDGES, edge_type, edge_imp,
        im_rows, im_cols, im_vals, icm_rows, icm_cols, icm_cls, icm_vals);

    // hop-0 att/ucls from fp32 inputs
    unsigned ablocks = (N_ENTITIES + N_USERS + TPB - 1) / TPB;
    attucls_kernel<<<ablocks, TPB>>>(entity_emb, user_emb, relation_emb, usr_cls_w);

    long long gw = (long long)(N_ENTITIES + N_USERS) * 32;
    unsigned gblocks = (unsigned)((gw + TPB - 1) / TPB);

    // hop 0: eh=A -> out B; residual init from inputs; epilogue computes hop-1 att/ucls
    gather_kernel<true><<<gblocks, TPB>>>(
        (const __half2*)p_ehA, relation_emb, usr_cls_w, (__half2*)p_ehB,
        (const float2*)entity_emb, (float2*)out_ent,
        p_u, (const float2*)user_emb, (float2*)out_usr);

    // hop 1: eh=B -> out A; residual accumulate; no epilogue att
    gather_kernel<false><<<gblocks, TPB>>>(
        (const __half2*)p_ehB, relation_emb, usr_cls_w, (__half2*)p_ehA,
        nullptr, (float2*)out_ent,
        p_u, nullptr, (float2*)out_usr);

    cor_kernel<<<1, 1>>>(disen, out_cor);
}

// round 7
// speedup vs baseline: 1.1286x; 1.1286x over previous
#include <cuda_runtime.h>
#include <cuda_fp16.h>
#include <cstdint>

#define N_ENTITIES 100000
#define N_USERS    50000
#define N_ITEMS    30000
#define D          64
#define N_REL      16
#define N_FACTORS  4
#define N_CLUSTERS 4
#define N_EDGES    1500000
#define NNZ_IM     1000000
#define NNZ_ICM    1000000
#define N_HOPS     2
#define TMP        0.2f

#define N_SEGS     (N_ENTITIES + N_USERS + N_USERS)   // 200000
#define IM_SEG0    N_ENTITIES
#define ICM_SEG0   (N_ENTITIES + N_USERS)
#define IM_BASE    N_EDGES
#define ICM_BASE   (N_EDGES + NNZ_IM)
#define TOT_NNZ    (N_EDGES + NNZ_IM + NNZ_ICM)       // 3.5M

#define SCAN_TILE  1024
#define N_TILES    ((N_SEGS + SCAN_TILE - 1) / SCAN_TILE)   // 196

#define CONV_N     (N_ENTITIES * D / 2)

// ---------------- scratch ----------------
__device__ float  g_att [N_ENTITIES * N_REL];
__device__ float  g_ucls[N_USERS * N_CLUSTERS];
__device__ __half g_ehA [N_ENTITIES * D];
__device__ __half g_ehB [N_ENTITIES * D];
__device__ float  g_u   [N_USERS * D];
__device__ float  g_relsum[D];

__device__ int   g_counts  [N_SEGS];
__device__ int   g_offsets [N_SEGS];
__device__ int   g_cursor  [N_SEGS];
__device__ int   g_tilesum [N_TILES];
__device__ int   g_tilebase[N_TILES];
__device__ int2  g_edge [N_EDGES];   // {tail | etype<<20, imp bits}
__device__ int2  g_im   [NNZ_IM];    // {col, val bits}
__device__ int2  g_icm  [NNZ_ICM];   // {col | cls<<16, val bits}

// ---------------- side-stream prep: fp16 convert + relsum ----------------
__global__ void convert_kernel(const float2* __restrict__ e2, __half2* __restrict__ eh,
                               const float* __restrict__ rel) {
    int i = blockIdx.x * blockDim.x + threadIdx.x;
    if (i < CONV_N) eh[i] = __float22half2_rn(e2[i]);
    if (i < D) {
        float s = 0.f;
#pragma unroll
        for (int r = 0; r < N_REL; r++) s += rel[r * D + i];
        g_relsum[i] = s;
    }
}

// ---------------- build ----------------
__global__ void zero_counts_kernel() {
    int i = blockIdx.x * blockDim.x + threadIdx.x;
    if (i < N_SEGS) g_counts[i] = 0;
}

__global__ void count_kernel(const int* __restrict__ head,
                             const int* __restrict__ im_rows,
                             const int* __restrict__ icm_rows) {
    int i = blockIdx.x * blockDim.x + threadIdx.x;
    if (i < N_EDGES) {
        atomicAdd(&g_counts[head[i]], 1);
    } else if (i < N_EDGES + NNZ_IM) {
        atomicAdd(&g_counts[IM_SEG0 + im_rows[i - N_EDGES]], 1);
    } else if (i < TOT_NNZ) {
        atomicAdd(&g_counts[ICM_SEG0 + icm_rows[i - N_EDGES - NNZ_IM]], 1);
    }
}

__global__ void scanA_kernel() {
    __shared__ int s[SCAN_TILE];
    int idx = blockIdx.x * SCAN_TILE + threadIdx.x;
    s[threadIdx.x] = (idx < N_SEGS) ? g_counts[idx] : 0;
    __syncthreads();
    for (int off = SCAN_TILE / 2; off > 0; off >>= 1) {
        if (threadIdx.x < off) s[threadIdx.x] += s[threadIdx.x + off];
        __syncthreads();
    }
    if (threadIdx.x == 0) g_tilesum[blockIdx.x] = s[0];
}

__global__ void scanB_kernel() {
    __shared__ int s[256];
    int t = threadIdx.x;
    int v = (t < N_TILES) ? g_tilesum[t] : 0;
    s[t] = v;
    __syncthreads();
    for (int off = 1; off < 256; off <<= 1) {
        int w = (t >= off) ? s[t - off] : 0;
        __syncthreads();
        s[t] += w;
        __syncthreads();
    }
    if (t < N_TILES) g_tilebase[t] = s[t] - v;
}

__global__ void scanC_kernel() {
    __shared__ int s[SCAN_TILE];
    int t = threadIdx.x;
    int idx = blockIdx.x * SCAN_TILE + t;
    int v = (idx < N_SEGS) ? g_counts[idx] : 0;
    s[t] = v;
    __syncthreads();
    for (int off = 1; off < SCAN_TILE; off <<= 1) {
        int w = (t >= off) ? s[t - off] : 0;
        __syncthreads();
        s[t] += w;
        __syncthreads();
    }
    if (idx < N_SEGS) {
        int excl = g_tilebase[blockIdx.x] + s[t] - v;
        g_offsets[idx] = excl;
        g_cursor[idx]  = excl;
    }
}

__global__ void fill_kernel(const int* __restrict__ head, const int* __restrict__ tail,
                            const int* __restrict__ etype, const float* __restrict__ eimp,
                            const int* __restrict__ im_rows, const int* __restrict__ im_cols,
                            const float* __restrict__ im_vals,
                            const int* __restrict__ icm_rows, const int* __restrict__ icm_cols,
                            const int* __restrict__ icm_cls, const float* __restrict__ icm_vals) {
    int i = blockIdx.x * blockDim.x + threadIdx.x;
    if (i < N_EDGES) {
        int h = head[i];
        int pos = atomicAdd(&g_cursor[h], 1);
        g_edge[pos] = make_int2(tail[i] | (etype[i] << 20), __float_as_int(eimp[i]));
    } else if (i < N_EDGES + NNZ_IM) {
        int j = i - N_EDGES;
        int r = im_rows[j];
        int pos = atomicAdd(&g_cursor[IM_SEG0 + r], 1) - IM_BASE;
        g_im[pos] = make_int2(im_cols[j], __float_as_int(im_vals[j]));
    } else if (i < TOT_NNZ) {
        int j = i - N_EDGES - NNZ_IM;
        int r = icm_rows[j];
        int pos = atomicAdd(&g_cursor[ICM_SEG0 + r], 1) - ICM_BASE;
        g_icm[pos] = make_int2(icm_cols[j] | (icm_cls[j] << 16), __float_as_int(icm_vals[j]));
    }
}

// ---------------- att/ucls (templated on entity source precision) ----------------
template <bool EFP16>
__global__ void attucls_kernel(const float* __restrict__ e32, const __half2* __restrict__ e16,
                               const float* __restrict__ u,
                               const float* __restrict__ rel, const float* __restrict__ w) {
    __shared__ float s_rel[N_REL * D];
    __shared__ float s_w[N_CLUSTERS * D];
    for (int i = threadIdx.x; i < N_REL * D; i += blockDim.x) s_rel[i] = rel[i];
    for (int i = threadIdx.x; i < N_CLUSTERS * D; i += blockDim.x) s_w[i] = w[i];
    __syncthreads();
    int i = blockIdx.x * blockDim.x + threadIdx.x;
    if (i < N_ENTITIES) {
        float acc[N_REL];
#pragma unroll
        for (int r = 0; r < N_REL; r++) acc[r] = 0.f;
        if (EFP16) {
            const __half2* row = e16 + (size_t)i * (D / 2);
#pragma unroll
            for (int k = 0; k < D / 2; k++) {
                float2 ev = __half22float2(row[k]);
#pragma unroll
                for (int r = 0; r < N_REL; r++) {
                    float2 rv = ((const float2*)(s_rel + r * D))[k];
                    acc[r] += ev.x * rv.x + ev.y * rv.y;
                }
            }
        } else {
            const float4* row = (const float4*)(e32 + (size_t)i * D);
#pragma unroll
            for (int k = 0; k < D / 4; k++) {
                float4 ev = row[k];
#pragma unroll
                for (int r = 0; r < N_REL; r++) {
                    float4 rv = ((const float4*)(s_rel + r * D))[k];
                    acc[r] += ev.x * rv.x + ev.y * rv.y + ev.z * rv.z + ev.w * rv.w;
                }
            }
        }
        float mx = acc[0];
#pragma unroll
        for (int r = 1; r < N_REL; r++) mx = fmaxf(mx, acc[r]);
        float sum = 0.f;
#pragma unroll
        for (int r = 0; r < N_REL; r++) { acc[r] = expf(acc[r] - mx); sum += acc[r]; }
        float inv = 1.f / sum;
#pragma unroll
        for (int r = 0; r < N_REL; r++) g_att[(size_t)i * N_REL + r] = acc[r] * inv;
    } else if (i < N_ENTITIES + N_USERS) {
        int uidx = i - N_ENTITIES;
        const float4* row = (const float4*)(u + (size_t)uidx * D);
        float acc[N_CLUSTERS] = {0.f, 0.f, 0.f, 0.f};
#pragma unroll
        for (int k = 0; k < D / 4; k++) {
            float4 uv = row[k];
#pragma unroll
            for (int c = 0; c < N_CLUSTERS; c++) {
                float4 wv = ((const float4*)(s_w + c * D))[k];
                acc[c] += uv.x * wv.x + uv.y * wv.y + uv.z * wv.z + uv.w * wv.w;
            }
        }
        float mx = fmaxf(fmaxf(acc[0], acc[1]), fmaxf(acc[2], acc[3]));
        float sum = 0.f;
#pragma unroll
        for (int c = 0; c < N_CLUSTERS; c++) { acc[c] = expf(acc[c] - mx); sum += acc[c]; }
        float inv = 1.f / sum;
#pragma unroll
        for (int c = 0; c < N_CLUSTERS; c++) g_ucls[(size_t)uidx * N_CLUSTERS + c] = acc[c] * inv;
    }
}

// ---------------- fused gather (warp per row; fp16 gathers; no atomics) ----------------
template <bool HOP0>
__global__ void gather_kernel(const __half2* __restrict__ eh,
                              const float* __restrict__ rel,
                              __half2* __restrict__ eh_out,
                              const float2* __restrict__ base_ent, float2* __restrict__ res_ent,
                              float* __restrict__ u_out,
                              const float2* __restrict__ base_usr, float2* __restrict__ res_usr) {
    __shared__ float2 s_rel[N_REL * 32];
    __shared__ float2 s_rs[32];
    for (int i = threadIdx.x; i < N_REL * 32; i += blockDim.x)
        s_rel[i] = ((const float2*)rel)[i];
    if (threadIdx.x < 32) s_rs[threadIdx.x] = ((const float2*)g_relsum)[threadIdx.x];
    __syncthreads();

    int warp = (blockIdx.x * blockDim.x + threadIdx.x) >> 5;
    int lane = threadIdx.x & 31;
    float2 acc = make_float2(0.f, 0.f);

    if (warp < N_ENTITIES) {
        int start = g_offsets[warp];
        int cnt   = g_counts[warp];
        const int2* ep = g_edge + start;
        const float* attrow = g_att + (size_t)warp * N_REL;
        int j = 0;
        for (; j + 4 <= cnt; j += 4) {
            int2 a0 = ep[j], a1 = ep[j + 1], a2 = ep[j + 2], a3 = ep[j + 3];
            int t0 = a0.x & 0xFFFFF, r0 = a0.x >> 20;
            int t1 = a1.x & 0xFFFFF, r1 = a1.x >> 20;
            int t2 = a2.x & 0xFFFFF, r2 = a2.x >> 20;
            int t3 = a3.x & 0xFFFFF, r3 = a3.x >> 20;
            float w0 = __int_as_float(a0.y) * attrow[r0];
            float w1 = __int_as_float(a1.y) * attrow[r1];
            float w2 = __int_as_float(a2.y) * attrow[r2];
            float w3 = __int_as_float(a3.y) * attrow[r3];
            float2 v0 = __half22float2(eh[(size_t)t0 * 32 + lane]);
            float2 v1 = __half22float2(eh[(size_t)t1 * 32 + lane]);
            float2 v2 = __half22float2(eh[(size_t)t2 * 32 + lane]);
            float2 v3 = __half22float2(eh[(size_t)t3 * 32 + lane]);
            float2 q0 = s_rel[r0 * 32 + lane];
            float2 q1 = s_rel[r1 * 32 + lane];
            float2 q2 = s_rel[r2 * 32 + lane];
            float2 q3 = s_rel[r3 * 32 + lane];
            acc.x += w0 * v0.x * q0.x + w1 * v1.x * q1.x + w2 * v2.x * q2.x + w3 * v3.x * q3.x;
            acc.y += w0 * v0.y * q0.y + w1 * v1.y * q1.y + w2 * v2.y * q2.y + w3 * v3.y * q3.y;
        }
        for (; j < cnt; j++) {
            int2 a = ep[j];
            int t = a.x & 0xFFFFF, r = a.x >> 20;
            float wv = __int_as_float(a.y) * attrow[r];
            float2 v = __half22float2(eh[(size_t)t * 32 + lane]);
            float2 q = s_rel[r * 32 + lane];
            acc.x += wv * v.x * q.x;
            acc.y += wv * v.y * q.y;
        }
        float ss = acc.x * acc.x + acc.y * acc.y;
#pragma unroll
        for (int o = 16; o; o >>= 1) ss += __shfl_xor_sync(0xffffffffu, ss, o);
        float inv = 1.f / fmaxf(sqrtf(ss), 1e-12f);
        float2 o2 = make_float2(acc.x * inv, acc.y * inv);
        eh_out[(size_t)warp * 32 + lane] = __float22half2_rn(o2);
        float2 cur = HOP0 ? base_ent[(size_t)warp * 32 + lane]
                          : res_ent[(size_t)warp * 32 + lane];
        cur.x += o2.x; cur.y += o2.y;
        res_ent[(size_t)warp * 32 + lane] = cur;
    } else if (warp < N_ENTITIES + N_USERS) {
        int uidx = warp - N_ENTITIES;
        float2 rs = s_rs[lane];
        const float* ucrow = g_ucls + (size_t)uidx * N_CLUSTERS;
        // im segment
        {
            int start = g_offsets[IM_SEG0 + uidx] - IM_BASE;
            int cnt   = g_counts[IM_SEG0 + uidx];
            const int2* ep = g_im + start;
            int j = 0;
            for (; j + 4 <= cnt; j += 4) {
                int2 a0 = ep[j], a1 = ep[j + 1], a2 = ep[j + 2], a3 = ep[j + 3];
                float2 v0 = __half22float2(eh[(size_t)a0.x * 32 + lane]);
                float2 v1 = __half22float2(eh[(size_t)a1.x * 32 + lane]);
                float2 v2 = __half22float2(eh[(size_t)a2.x * 32 + lane]);
                float2 v3 = __half22float2(eh[(size_t)a3.x * 32 + lane]);
                float w0 = __int_as_float(a0.y), w1 = __int_as_float(a1.y);
                float w2 = __int_as_float(a2.y), w3 = __int_as_float(a3.y);
                acc.x += w0 * v0.x + w1 * v1.x + w2 * v2.x + w3 * v3.x;
                acc.y += w0 * v0.y + w1 * v1.y + w2 * v2.y + w3 * v3.y;
            }
            for (; j < cnt; j++) {
                int2 a = ep[j];
                float2 v = __half22float2(eh[(size_t)a.x * 32 + lane]);
                float w = __int_as_float(a.y);
                acc.x += w * v.x;
                acc.y += w * v.y;
            }
        }
        // icm segment (fused dw einsum)
        float2 acc2 = make_float2(0.f, 0.f);
        {
            int start = g_offsets[ICM_SEG0 + uidx] - ICM_BASE;
            int cnt   = g_counts[ICM_SEG0 + uidx];
            const int2* ep = g_icm + start;
            int j = 0;
            for (; j + 4 <= cnt; j += 4) {
                int2 a0 = ep[j], a1 = ep[j + 1], a2 = ep[j + 2], a3 = ep[j + 3];
                int c0 = a0.x & 0xFFFF, k0 = a0.x >> 16;
                int c1 = a1.x & 0xFFFF, k1 = a1.x >> 16;
                int c2 = a2.x & 0xFFFF, k2 = a2.x >> 16;
                int c3 = a3.x & 0xFFFF, k3 = a3.x >> 16;
                float w0 = __int_as_float(a0.y) * ucrow[k0];
                float w1 = __int_as_float(a1.y) * ucrow[k1];
                float w2 = __int_as_float(a2.y) * ucrow[k2];
                float w3 = __int_as_float(a3.y) * ucrow[k3];
                float2 v0 = __half22float2(eh[(size_t)c0 * 32 + lane]);
                float2 v1 = __half22float2(eh[(size_t)c1 * 32 + lane]);
                float2 v2 = __half22float2(eh[(size_t)c2 * 32 + lane]);
                float2 v3 = __half22float2(eh[(size_t)c3 * 32 + lane]);
                acc2.x += w0 * v0.x + w1 * v1.x + w2 * v2.x + w3 * v3.x;
                acc2.y += w0 * v0.y + w1 * v1.y + w2 * v2.y + w3 * v3.y;
            }
            for (; j < cnt; j++) {
                int2 a = ep[j];
                int c = a.x & 0xFFFF, k = a.x >> 16;
                float w = __int_as_float(a.y) * ucrow[k];
                float2 v = __half22float2(eh[(size_t)c * 32 + lane]);
                acc2.x += w * v.x;
                acc2.y += w * v.y;
            }
        }
        acc.x += acc2.x * rs.x;
        acc.y += acc2.y * rs.y;

        float ss = acc.x * acc.x + acc.y * acc.y;
#pragma unroll
        for (int o = 16; o; o >>= 1) ss += __shfl_xor_sync(0xffffffffu, ss, o);
        float inv = 1.f / fmaxf(sqrtf(ss), 1e-12f);
        float2 o2 = make_float2(acc.x * inv, acc.y * inv);
        ((float2*)(u_out + (size_t)uidx * D))[lane] = o2;
        float2 cur = HOP0 ? base_usr[(size_t)uidx * 32 + lane]
                          : res_usr[(size_t)uidx * 32 + lane];
        cur.x += o2.x; cur.y += o2.y;
        res_usr[(size_t)uidx * 32 + lane] = cur;
    }
}

// ---------------- cor loss ----------------
__global__ void cor_kernel(const float* __restrict__ dw, float* __restrict__ out) {
    float nt[N_FACTORS][N_REL];
#pragma unroll
    for (int c = 0; c < N_FACTORS; c++) {
        float ss = 0.f;
#pragma unroll
        for (int k = 0; k < N_REL; k++) { float x = dw[c * N_REL + k]; ss += x * x; }
        float inv = 1.f / fmaxf(sqrtf(ss), 1e-12f);
#pragma unroll
        for (int k = 0; k < N_REL; k++) nt[c][k] = dw[c * N_REL + k] * inv;
    }
    float loss = 0.f;
#pragma unroll
    for (int i = 0; i < N_FACTORS; i++) {
        float ssum = 0.f, diag = 0.f;
#pragma unroll
        for (int j = 0; j < N_FACTORS; j++) {
            float dot = 0.f;
#pragma unroll
            for (int k = 0; k < N_REL; k++) dot += nt[i][k] * nt[j][k];
            float s = expf(dot / TMP);
            ssum += s;
            if (i == j) diag = s;
        }
        loss -= logf(diag / ssum);
    }
    out[0] = loss;
}

// ---------------- launch ----------------
extern "C" void kernel_launch(void* const* d_in, const int* in_sizes, int n_in,
                              void* d_out, int out_size) {
    const float* user_emb     = (const float*)d_in[0];
    const float* entity_emb   = (const float*)d_in[1];
    const float* relation_emb = (const float*)d_in[3];
    const float* disen        = (const float*)d_in[4];
    const float* usr_cls_w    = (const float*)d_in[5];
    const float* edge_imp     = (const float*)d_in[6];
    const float* im_vals      = (const float*)d_in[7];
    const float* icm_vals     = (const float*)d_in[8];
    const int*   edge_index   = (const int*)d_in[9];
    const int*   edge_type    = (const int*)d_in[10];
    const int*   im_rows      = (const int*)d_in[11];
    const int*   im_cols      = (const int*)d_in[12];
    const int*   icm_cls      = (const int*)d_in[13];
    const int*   icm_rows     = (const int*)d_in[14];
    const int*   icm_cols     = (const int*)d_in[15];

    float* out     = (float*)d_out;
    float* out_ent = out;
    float* out_usr = out + (size_t)N_ENTITIES * D;
    float* out_cor = out + (size_t)N_ENTITIES * D + (size_t)N_USERS * D;

    __half *p_ehA, *p_ehB;
    float *p_u;
    cudaGetSymbolAddress((void**)&p_ehA, g_ehA);
    cudaGetSymbolAddress((void**)&p_ehB, g_ehB);
    cudaGetSymbolAddress((void**)&p_u, g_u);

    // lazy one-time host resources (created on the uncaptured correctness run)
    static cudaStream_t s_side = nullptr;
    static cudaEvent_t ev_fork = nullptr, ev_join = nullptr;
    if (s_side == nullptr) {
        cudaStreamCreateWithFlags(&s_side, cudaStreamNonBlocking);
        cudaEventCreateWithFlags(&ev_fork, cudaEventDisableTiming);
        cudaEventCreateWithFlags(&ev_join, cudaEventDisableTiming);
    }

    const int TPB = 256;
    unsigned ablocks = (N_ENTITIES + N_USERS + TPB - 1) / TPB;
    long long gw = (long long)(N_ENTITIES + N_USERS) * 32;
    unsigned gblocks = (unsigned)((gw + TPB - 1) / TPB);

    // ---- fork side stream: convert+relsum, hop-0 att/ucls, cor loss ----
    cudaEventRecord(ev_fork, 0);
    cudaStreamWaitEvent(s_side, ev_fork, 0);
    convert_kernel<<<(CONV_N + TPB - 1) / TPB, TPB, 0, s_side>>>(
        (const float2*)entity_emb, (__half2*)p_ehA, relation_emb);
    attucls_kernel<false><<<ablocks, TPB, 0, s_side>>>(
        entity_emb, nullptr, user_emb, relation_emb, usr_cls_w);
    cor_kernel<<<1, 1, 0, s_side>>>(disen, out_cor);
    cudaEventRecord(ev_join, s_side);

    // ---- main stream: CSR build chain ----
    zero_counts_kernel<<<(N_SEGS + TPB - 1) / TPB, TPB>>>();
    count_kernel<<<(TOT_NNZ + TPB - 1) / TPB, TPB>>>(edge_index, im_rows, icm_rows);
    scanA_kernel<<<N_TILES, SCAN_TILE>>>();
    scanB_kernel<<<1, 256>>>();
    scanC_kernel<<<N_TILES, SCAN_TILE>>>();
    fill_kernel<<<(TOT_NNZ + TPB - 1) / TPB, TPB>>>(
        edge_index, edge_index + N_EDGES, edge_type, edge_imp,
        im_rows, im_cols, im_vals, icm_rows, icm_cols, icm_cls, icm_vals);

    // ---- join ----
    cudaStreamWaitEvent(0, ev_join, 0);

    // hop 0: eh=A -> B; residual init from inputs
    gather_kernel<true><<<gblocks, TPB>>>(
        (const __half2*)p_ehA, relation_emb, (__half2*)p_ehB,
        (const float2*)entity_emb, (float2*)out_ent,
        p_u, (const float2*)user_emb, (float2*)out_usr);

    // hop-1 att/ucls from fp16 entity + fp32 user
    attucls_kernel<true><<<ablocks, TPB>>>(
        nullptr, (const __half2*)p_ehB, p_u, relation_emb, usr_cls_w);

    // hop 1: eh=B -> A; residual accumulate
    gather_kernel<false><<<gblocks, TPB>>>(
        (const __half2*)p_ehB, relation_emb, (__half2*)p_ehA,
        nullptr, (float2*)out_ent,
        p_u, nullptr, (float2*)out_usr);
}